// round 2
// baseline (speedup 1.0000x reference)
#include <cuda_runtime.h>
#include <stdint.h>

// Haar DWT level-1: x (8,32,512,512) fp32 -> (LL,LH,HL,HH) each (8,32,256,256)
// d_out layout: [LL | LH | HL | HH], each band 16,777,216 floats.
//
// Each thread: 4 x LDG.128 (rows 2oy,2oy+1; cols 8*px4..8*px4+7),
// produces 4 output columns for all 4 bands -> 4 x STG.128.
// Streaming cache hints (__ldcs/__stcs): data touched exactly once.

#define H_IN   512
#define W_IN   512
#define H_OUT  256
#define W_OUT  256
#define N_IMG  256                           // 8*32
#define BAND_ELEMS (N_IMG * H_OUT * W_OUT)   // 16,777,216
#define QUADS_PER_ROW (W_OUT / 4)            // 64 float4 outputs per row

__global__ __launch_bounds__(256)
void haar_dwt_kernel(const float* __restrict__ x, float* __restrict__ out) {
    // One thread per (img, oy, px4): total = 256*256*64 = 4,194,304 threads.
    unsigned idx = blockIdx.x * blockDim.x + threadIdx.x;

    unsigned px4 = idx & (QUADS_PER_ROW - 1);           // 0..63
    unsigned t   = idx >> 6;                            // img*256 + oy
    unsigned oy  = t & (H_OUT - 1);                     // 0..255
    unsigned img = t >> 8;                              // 0..255

    const float* base = x + ((size_t)img * H_IN + (size_t)(2 * oy)) * W_IN + 8 * px4;
    const float4* b4 = reinterpret_cast<const float4*>(base);

    // Front-batch all 4 loads (MLP=4).
    float4 r0a = __ldcs(b4);                 // row 2oy,   cols 0..3
    float4 r0b = __ldcs(b4 + 1);             // row 2oy,   cols 4..7
    float4 r1a = __ldcs(b4 + W_IN / 4);      // row 2oy+1, cols 0..3
    float4 r1b = __ldcs(b4 + W_IN / 4 + 1);  // row 2oy+1, cols 4..7

    const float q = 0.25f;

    // pair k: a=top even, b=top odd, c=bot even, d=bot odd
    // s0=a+b, s1=c+d, d0=b-a, d1=d-c
    // LL=q(s0+s1)  LH=q(s1-s0)  HL=q(d0+d1)  HH=q(d1-d0)
    float s0, s1, dd0, dd1;
    float4 ll, lh, hl, hh;

    s0 = r0a.x + r0a.y; s1 = r1a.x + r1a.y; dd0 = r0a.y - r0a.x; dd1 = r1a.y - r1a.x;
    ll.x = q*(s0+s1); lh.x = q*(s1-s0); hl.x = q*(dd0+dd1); hh.x = q*(dd1-dd0);

    s0 = r0a.z + r0a.w; s1 = r1a.z + r1a.w; dd0 = r0a.w - r0a.z; dd1 = r1a.w - r1a.z;
    ll.y = q*(s0+s1); lh.y = q*(s1-s0); hl.y = q*(dd0+dd1); hh.y = q*(dd1-dd0);

    s0 = r0b.x + r0b.y; s1 = r1b.x + r1b.y; dd0 = r0b.y - r0b.x; dd1 = r1b.y - r1b.x;
    ll.z = q*(s0+s1); lh.z = q*(s1-s0); hl.z = q*(dd0+dd1); hh.z = q*(dd1-dd0);

    s0 = r0b.z + r0b.w; s1 = r1b.z + r1b.w; dd0 = r0b.w - r0b.z; dd1 = r1b.w - r1b.z;
    ll.w = q*(s0+s1); lh.w = q*(s1-s0); hl.w = q*(dd0+dd1); hh.w = q*(dd1-dd0);

    // Output offset within a band in float4 units.
    size_t o = ((size_t)img * H_OUT + oy) * QUADS_PER_ROW + px4;

    float4* outp = reinterpret_cast<float4*>(out);
    const size_t band4 = BAND_ELEMS / 4;   // band stride in float4 units
    __stcs(outp + o,             ll);
    __stcs(outp + o +     band4, lh);
    __stcs(outp + o + 2 * band4, hl);
    __stcs(outp + o + 3 * band4, hh);
}

extern "C" void kernel_launch(void* const* d_in, const int* in_sizes, int n_in,
                              void* d_out, int out_size) {
    const float* x = (const float*)d_in[0];
    float* out = (float*)d_out;

    const unsigned total_threads = N_IMG * H_OUT * QUADS_PER_ROW;  // 4,194,304
    const unsigned block = 256;
    const unsigned grid = total_threads / block;                   // 16384

    haar_dwt_kernel<<<grid, block>>>(x, out);
}

// round 3
// speedup vs baseline: 1.0027x; 1.0027x over previous
#include <cuda_runtime.h>
#include <stdint.h>

// Haar DWT level-1: x (8,32,512,512) fp32 -> (LL,LH,HL,HH) each (8,32,256,256)
// d_out layout: [LL | LH | HL | HH], each band 16,777,216 floats.
//
// Each thread handles TWO output rows (oy and oy+128) x 4 output columns:
// 8 front-batched LDG.128 (MLP=8), 8 STG.128. Plain cache policy.

#define H_IN   512
#define W_IN   512
#define H_OUT  256
#define W_OUT  256
#define N_IMG  256                           // 8*32
#define BAND_ELEMS (N_IMG * H_OUT * W_OUT)   // 16,777,216
#define QUADS_PER_ROW (W_OUT / 4)            // 64 float4 outputs per row
#define OYP    (H_OUT / 2)                   // 128

__device__ __forceinline__ void haar4(float4 r0a, float4 r0b, float4 r1a, float4 r1b,
                                      float4& ll, float4& lh, float4& hl, float4& hh) {
    const float q = 0.25f;
    float s0, s1, d0, d1;

    s0 = r0a.x + r0a.y; s1 = r1a.x + r1a.y; d0 = r0a.y - r0a.x; d1 = r1a.y - r1a.x;
    ll.x = q*(s0+s1); lh.x = q*(s1-s0); hl.x = q*(d0+d1); hh.x = q*(d1-d0);

    s0 = r0a.z + r0a.w; s1 = r1a.z + r1a.w; d0 = r0a.w - r0a.z; d1 = r1a.w - r1a.z;
    ll.y = q*(s0+s1); lh.y = q*(s1-s0); hl.y = q*(d0+d1); hh.y = q*(d1-d0);

    s0 = r0b.x + r0b.y; s1 = r1b.x + r1b.y; d0 = r0b.y - r0b.x; d1 = r1b.y - r1b.x;
    ll.z = q*(s0+s1); lh.z = q*(s1-s0); hl.z = q*(d0+d1); hh.z = q*(d1-d0);

    s0 = r0b.z + r0b.w; s1 = r1b.z + r1b.w; d0 = r0b.w - r0b.z; d1 = r1b.w - r1b.z;
    ll.w = q*(s0+s1); lh.w = q*(s1-s0); hl.w = q*(d0+d1); hh.w = q*(d1-d0);
}

__global__ __launch_bounds__(256)
void haar_dwt_kernel(const float* __restrict__ x, float* __restrict__ out) {
    // One thread per (img, oyp, px4): total = 256*128*64 = 2,097,152 threads.
    unsigned idx = blockIdx.x * blockDim.x + threadIdx.x;

    unsigned px4 = idx & (QUADS_PER_ROW - 1);           // 0..63
    unsigned t   = idx >> 6;
    unsigned oyp = t & (OYP - 1);                        // 0..127
    unsigned img = t >> 7;                               // 0..255

    unsigned oy0 = oyp;            // first output row
    unsigned oy1 = oyp + OYP;      // second output row (+128)

    const float4* x4 = reinterpret_cast<const float4*>(x);
    size_t rowq = W_IN / 4;  // 128 float4 per input row
    size_t base0 = ((size_t)img * H_IN + 2 * oy0) * rowq + 2 * px4;
    size_t base1 = ((size_t)img * H_IN + 2 * oy1) * rowq + 2 * px4;

    // Front-batch all 8 loads (MLP=8).
    float4 A0 = x4[base0];                // row 2oy0, cols 0..3
    float4 A1 = x4[base0 + 1];            // row 2oy0, cols 4..7
    float4 B0 = x4[base0 + rowq];         // row 2oy0+1
    float4 B1 = x4[base0 + rowq + 1];
    float4 C0 = x4[base1];                // row 2oy1
    float4 C1 = x4[base1 + 1];
    float4 D0 = x4[base1 + rowq];         // row 2oy1+1
    float4 D1 = x4[base1 + rowq + 1];

    float4 ll0, lh0, hl0, hh0, ll1, lh1, hl1, hh1;
    haar4(A0, A1, B0, B1, ll0, lh0, hl0, hh0);
    haar4(C0, C1, D0, D1, ll1, lh1, hl1, hh1);

    float4* outp = reinterpret_cast<float4*>(out);
    const size_t band4 = BAND_ELEMS / 4;   // band stride in float4 units
    size_t o0 = ((size_t)img * H_OUT + oy0) * QUADS_PER_ROW + px4;
    size_t o1 = ((size_t)img * H_OUT + oy1) * QUADS_PER_ROW + px4;

    outp[o0]             = ll0;
    outp[o1]             = ll1;
    outp[o0 +     band4] = lh0;
    outp[o1 +     band4] = lh1;
    outp[o0 + 2 * band4] = hl0;
    outp[o1 + 2 * band4] = hl1;
    outp[o0 + 3 * band4] = hh0;
    outp[o1 + 3 * band4] = hh1;
}

extern "C" void kernel_launch(void* const* d_in, const int* in_sizes, int n_in,
                              void* d_out, int out_size) {
    const float* x = (const float*)d_in[0];
    float* out = (float*)d_out;

    const unsigned total_threads = N_IMG * OYP * QUADS_PER_ROW;  // 2,097,152
    const unsigned block = 256;
    const unsigned grid = total_threads / block;                 // 8192

    haar_dwt_kernel<<<grid, block>>>(x, out);
}

// round 4
// speedup vs baseline: 1.0130x; 1.0102x over previous
#include <cuda_runtime.h>
#include <stdint.h>

// Haar DWT level-1: x (8,32,512,512) fp32 -> (LL,LH,HL,HH) each (8,32,256,256)
// d_out layout: [LL | LH | HL | HH], each band 16,777,216 floats.
//
// Final form: lightest-weight thread (R1 structure — best measured, 20 regs),
// 2x LDG.128 + 4x STG.64 per thread, block=512.
// Kernel is pinned at the DRAM mixed-R/W ceiling (~6.5 TB/s, 81% of spec);
// traffic is at the 537 MB information-theoretic floor.

#define H_IN   512
#define W_IN   512
#define H_OUT  256
#define W_OUT  256
#define N_IMG  256                           // 8*32
#define BAND_ELEMS (N_IMG * H_OUT * W_OUT)   // 16,777,216
#define PAIRS_PER_ROW (W_OUT / 2)            // 128

__global__ __launch_bounds__(512)
void haar_dwt_kernel(const float* __restrict__ x, float* __restrict__ out) {
    // One thread per (img, oy, px): total = 256*256*128 = 8,388,608.
    unsigned idx = blockIdx.x * blockDim.x + threadIdx.x;

    unsigned px  = idx & (PAIRS_PER_ROW - 1);          // 0..127
    unsigned t   = idx >> 7;                            // img*256 + oy
    unsigned oy  = t & (H_OUT - 1);                     // 0..255
    unsigned img = t >> 8;                              // 0..255

    const float* base = x + ((size_t)img * H_IN + (size_t)(2 * oy)) * W_IN + 4 * px;
    float4 r0 = *reinterpret_cast<const float4*>(base);          // row 2oy
    float4 r1 = *reinterpret_cast<const float4*>(base + W_IN);   // row 2oy+1

    const float q = 0.25f;

    // Pair 0: a=r0.x b=r0.y c=r1.x d=r1.y ; Pair 1: a=r0.z b=r0.w c=r1.z d=r1.w
    float s0a = r0.x + r0.y, s1a = r1.x + r1.y;
    float d0a = r0.y - r0.x, d1a = r1.y - r1.x;
    float s0b = r0.z + r0.w, s1b = r1.z + r1.w;
    float d0b = r0.w - r0.z, d1b = r1.w - r1.z;

    float2 ll = make_float2(q * (s0a + s1a), q * (s0b + s1b));   //  a+b+c+d
    float2 lh = make_float2(q * (s1a - s0a), q * (s1b - s0b));   // -a-b+c+d
    float2 hl = make_float2(q * (d0a + d1a), q * (d0b + d1b));   // -a+b-c+d
    float2 hh = make_float2(q * (d1a - d0a), q * (d1b - d0b));   //  a-b-c+d

    size_t o = ((size_t)img * H_OUT + oy) * PAIRS_PER_ROW + px;

    float2* outp = reinterpret_cast<float2*>(out);
    const size_t band2 = BAND_ELEMS / 2;   // band stride in float2 units
    outp[o]             = ll;
    outp[o + band2]     = lh;
    outp[o + 2 * band2] = hl;
    outp[o + 3 * band2] = hh;
}

extern "C" void kernel_launch(void* const* d_in, const int* in_sizes, int n_in,
                              void* d_out, int out_size) {
    const float* x = (const float*)d_in[0];
    float* out = (float*)d_out;

    const unsigned total_threads = N_IMG * H_OUT * PAIRS_PER_ROW;  // 8,388,608
    const unsigned block = 512;
    const unsigned grid = total_threads / block;                   // 16384

    haar_dwt_kernel<<<grid, block>>>(x, out);
}